// round 1
// baseline (speedup 1.0000x reference)
#include <cuda_runtime.h>
#include <cuda_bf16.h>
#include <cstdint>

#define NUM_CLASSES 1000
#define FEAT_DIM    512
#define BATCH       32768
#define ALPHA       0.5f

// -------- scratch (no allocations allowed; __device__ globals) --------
struct Scratch {
    double loss;                 // global loss accumulator
    int    counts[NUM_CLASSES];  // histogram
    int    cursor[NUM_CLASSES];  // scatter cursors (exclusive offsets)
    int    flag_i32;             // 1 if labels buffer is int32, 0 if int64
};
__device__ Scratch g_s;
__device__ int g_offsets[NUM_CLASSES + 1];
__device__ int g_idx[BATCH];     // row indices sorted by class

// -------- label access helper (handles int32 or int64 labels) --------
__device__ __forceinline__ int get_label(const void* labels, int i) {
    if (g_s.flag_i32)
        return ((const int*)labels)[i];
    return (int)(((const long long*)labels)[i]);
}

// K0: detect label dtype. View buffer as int32. If data is int64, every odd
// 32-bit word is the high half of a value < 1000 -> exactly 0. If data is
// int32, odd words are labels[1,3,5,...] and are nonzero w.h.p. (p(all 16384
// are zero) ~ 0). Only read the first 32768 int32 words: safe for both widths.
__global__ void k_detect(const void* labels) {
    int t = blockIdx.x * blockDim.x + threadIdx.x;   // 0..16383
    if (t < BATCH / 2) {
        int w = ((const int*)labels)[2 * t + 1];
        if (w != 0) g_s.flag_i32 = 1;                // benign race, same value
    }
}

// K1: histogram of labels
__global__ void k_hist(const void* labels) {
    int i = blockIdx.x * blockDim.x + threadIdx.x;
    if (i < BATCH) {
        int c = get_label(labels, i);
        atomicAdd(&g_s.counts[c], 1);
    }
}

// K2: exclusive prefix-sum over 1000 counts (single block, 1024 threads)
__global__ void k_scan() {
    __shared__ int s[1024];
    int t = threadIdx.x;
    int v = (t < NUM_CLASSES) ? g_s.counts[t] : 0;
    s[t] = v;
    __syncthreads();
    // Hillis-Steele inclusive scan
    for (int off = 1; off < 1024; off <<= 1) {
        int x = (t >= off) ? s[t - off] : 0;
        __syncthreads();
        s[t] += x;
        __syncthreads();
    }
    if (t < NUM_CLASSES) {
        g_offsets[t + 1] = s[t];
        g_s.cursor[t]    = s[t] - v;   // exclusive offset for scatter
    }
    if (t == 0) g_offsets[0] = 0;
}

// K3: scatter row indices into class-contiguous order
__global__ void k_scatter(const void* labels) {
    int i = blockIdx.x * blockDim.x + threadIdx.x;
    if (i < BATCH) {
        int c = get_label(labels, i);
        int pos = atomicAdd(&g_s.cursor[c], 1);
        g_idx[pos] = i;
    }
}

// K4: one block per class. 128 threads, each owns one float4 (4 feature dims).
// Streams the class's feature rows ONCE: accumulates sum (for the mean) and
// squared diff vs the class center (for the loss). Then writes the EMA-updated
// center and atomically accumulates the block's loss partial.
__global__ void __launch_bounds__(128, 8) k_main(
    const float4* __restrict__ feat,   // [BATCH * 128] float4
    const float4* __restrict__ cen,    // [NUM_CLASSES * 128] float4
    float* __restrict__ out)           // d_out
{
    const int c = blockIdx.x;
    const int t = threadIdx.x;         // 0..127

    float4 c4 = cen[c * 128 + t];

    const int beg = g_offsets[c];
    const int end = g_offsets[c + 1];

    float sx = 0.f, sy = 0.f, sz = 0.f, sw = 0.f;
    float lp = 0.f;

    __shared__ int sidx[256];
    for (int base = beg; base < end; base += 256) {
        int n = min(256, end - base);
        for (int k = t; k < n; k += 128) sidx[k] = g_idx[base + k];
        __syncthreads();
        #pragma unroll 4
        for (int j = 0; j < n; j++) {
            float4 f = feat[(size_t)sidx[j] * 128 + t];
            sx += f.x; sy += f.y; sz += f.z; sw += f.w;
            float dx = f.x - c4.x, dy = f.y - c4.y;
            float dz = f.z - c4.z, dw = f.w - c4.w;
            lp += dx * dx + dy * dy + dz * dz + dw * dw;
        }
        __syncthreads();
    }

    // center update
    const int cnt = end - beg;
    float4 nc;
    if (cnt > 0) {
        float inv = ALPHA / (float)cnt;
        nc.x = (1.f - ALPHA) * c4.x + sx * inv;
        nc.y = (1.f - ALPHA) * c4.y + sy * inv;
        nc.z = (1.f - ALPHA) * c4.z + sz * inv;
        nc.w = (1.f - ALPHA) * c4.w + sw * inv;
    } else {
        nc = c4;
    }
    // output layout: out[0] = loss, out[1..] = new_centers (loss shifts
    // alignment by 4B, so scalar stores)
    float* ncp = out + 1 + (size_t)c * FEAT_DIM + t * 4;
    ncp[0] = nc.x; ncp[1] = nc.y; ncp[2] = nc.z; ncp[3] = nc.w;

    // block-reduce loss partial
    #pragma unroll
    for (int o = 16; o > 0; o >>= 1)
        lp += __shfl_xor_sync(0xFFFFFFFFu, lp, o);
    __shared__ float wr[4];
    if ((t & 31) == 0) wr[t >> 5] = lp;
    __syncthreads();
    if (t == 0) {
        double tot = (double)wr[0] + (double)wr[1] + (double)wr[2] + (double)wr[3];
        atomicAdd(&g_s.loss, tot);
    }
}

// K5: finalize loss
__global__ void k_finalize(float* out) {
    out[0] = (float)(0.5 * g_s.loss / (double)BATCH);
}

extern "C" void kernel_launch(void* const* d_in, const int* in_sizes, int n_in,
                              void* d_out, int out_size) {
    const float* features = (const float*)d_in[0];
    const void*  labels   = d_in[1];
    const float* centers  = (const float*)d_in[2];
    float* out = (float*)d_out;

    void* sp = nullptr;
    cudaGetSymbolAddress(&sp, g_s);
    cudaMemsetAsync(sp, 0, sizeof(Scratch));

    k_detect<<<(BATCH / 2 + 255) / 256, 256>>>(labels);
    k_hist<<<(BATCH + 255) / 256, 256>>>(labels);
    k_scan<<<1, 1024>>>();
    k_scatter<<<(BATCH + 255) / 256, 256>>>(labels);
    k_main<<<NUM_CLASSES, 128>>>((const float4*)features, (const float4*)centers, out);
    k_finalize<<<1, 1>>>(out);
}

// round 4
// speedup vs baseline: 1.0094x; 1.0094x over previous
#include <cuda_runtime.h>
#include <cuda_bf16.h>
#include <cstdint>

#define NUM_CLASSES 1000
#define FEAT_DIM    512
#define BATCH       32768
#define ALPHA       0.5f

#define NB 128      // persistent front-kernel blocks (must all be resident; 128 <= 148 SMs)
#define NT 256

// -------- scratch (zeroed each replay by the memset node) --------
struct Scratch {
    double   loss;
    unsigned bar_arrive;
    unsigned bar_release;
    int      flag_i32;           // 1 if labels are int32, 0 if int64
    int      ticket;             // main-kernel finalize ticket
    int      counts[NUM_CLASSES];
    int      cursor[NUM_CLASSES];
};
__device__ Scratch g_s;
__device__ int g_offsets[NUM_CLASSES + 1];
__device__ int g_idx[BATCH];

// -------- software grid barrier (all NB blocks resident) --------
__device__ __forceinline__ void grid_bar(unsigned gen) {
    __syncthreads();
    if (threadIdx.x == 0) {
        __threadfence();
        unsigned t = atomicAdd(&g_s.bar_arrive, 1u) + 1u;
        if (t == (unsigned)NB * gen) {
            atomicExch(&g_s.bar_release, gen);
        } else {
            while (atomicAdd(&g_s.bar_release, 0u) < gen) { __nanosleep(64); }
        }
        __threadfence();
    }
    __syncthreads();
}

__device__ __forceinline__ int get_label(const void* labels, int i, int f32) {
    if (f32) return ((const int*)labels)[i];
    return (int)(((const long long*)labels)[i]);
}

// ===================== Kernel A: detect + hist + scan + scatter =====================
__global__ void __launch_bounds__(NT, 1) k_front(const void* __restrict__ labels) {
    const int t   = threadIdx.x;
    const int gid = blockIdx.x * NT + t;          // 0..32767

    // ---- Phase 0: label-width detect ----
    // View buffer as int32. If labels are int64 (<1000), every odd word is 0.
    // If int32, odd words are labels[1,3,...]: all-zero has prob ~(1/1000)^16384.
    // Only the first BATCH int32 words are read: in-bounds for both widths.
    if (gid < BATCH / 2) {
        int w = ((const int*)labels)[2 * gid + 1];
        if (w != 0) g_s.flag_i32 = 1;             // benign race, same value
    }
    grid_bar(1);

    const int f32 = g_s.flag_i32;

    // ---- Phase 1: histogram (REDG, result unused) ----
    {
        int c = get_label(labels, gid, f32);
        atomicAdd(&g_s.counts[c], 1);
    }
    grid_bar(2);

    // ---- Phase 2: exclusive scan over 1000 counts (block 0 only) ----
    if (blockIdx.x == 0) {
        __shared__ int ts[NT];
        const int base = 4 * t;                   // each thread: 4 classes
        int v[4], inc[4];
        #pragma unroll
        for (int k = 0; k < 4; k++)
            v[k] = (base + k < NUM_CLASSES) ? g_s.counts[base + k] : 0;
        inc[0] = v[0];
        #pragma unroll
        for (int k = 1; k < 4; k++) inc[k] = inc[k - 1] + v[k];
        ts[t] = inc[3];
        __syncthreads();
        for (int off = 1; off < NT; off <<= 1) {
            int x = (t >= off) ? ts[t - off] : 0;
            __syncthreads();
            ts[t] += x;
            __syncthreads();
        }
        int excl = (t > 0) ? ts[t - 1] : 0;
        #pragma unroll
        for (int k = 0; k < 4; k++) {
            if (base + k < NUM_CLASSES) {
                g_offsets[base + k + 1]  = excl + inc[k];
                g_s.cursor[base + k]     = excl + inc[k] - v[k];
            }
        }
        if (t == 0) g_offsets[0] = 0;
    }
    grid_bar(3);

    // ---- Phase 3: scatter row indices into class-contiguous order ----
    {
        int c = get_label(labels, gid, f32);
        int pos = atomicAdd(&g_s.cursor[c], 1);
        g_idx[pos] = gid;
    }
}

// ===================== Kernel B: per-class stream + EMA + loss =====================
__global__ void __launch_bounds__(128, 8) k_main(
    const float4* __restrict__ feat,   // [BATCH * 128] float4
    const float4* __restrict__ cen,    // [NUM_CLASSES * 128] float4
    float* __restrict__ out)
{
    const int c = blockIdx.x;
    const int t = threadIdx.x;         // 0..127

    float4 c4 = cen[c * 128 + t];

    const int beg = g_offsets[c];
    const int end = g_offsets[c + 1];

    float sx = 0.f, sy = 0.f, sz = 0.f, sw = 0.f;
    float lp = 0.f;

    __shared__ int sidx[256];
    for (int base = beg; base < end; base += 256) {
        int n = min(256, end - base);
        for (int k = t; k < n; k += 128) sidx[k] = g_idx[base + k];
        __syncthreads();
        #pragma unroll 8
        for (int j = 0; j < n; j++) {
            float4 f = feat[(size_t)sidx[j] * 128 + t];
            sx += f.x; sy += f.y; sz += f.z; sw += f.w;
            float dx = f.x - c4.x, dy = f.y - c4.y;
            float dz = f.z - c4.z, dw = f.w - c4.w;
            lp += dx * dx + dy * dy + dz * dz + dw * dw;
        }
        __syncthreads();
    }

    const int cnt = end - beg;
    float4 nc;
    if (cnt > 0) {
        float inv = ALPHA / (float)cnt;
        nc.x = (1.f - ALPHA) * c4.x + sx * inv;
        nc.y = (1.f - ALPHA) * c4.y + sy * inv;
        nc.z = (1.f - ALPHA) * c4.z + sz * inv;
        nc.w = (1.f - ALPHA) * c4.w + sw * inv;
    } else {
        nc = c4;
    }
    // out[0] = loss; out[1..] = new_centers (+1 shift -> scalar stores)
    float* ncp = out + 1 + (size_t)c * FEAT_DIM + t * 4;
    ncp[0] = nc.x; ncp[1] = nc.y; ncp[2] = nc.z; ncp[3] = nc.w;

    // block loss reduce
    #pragma unroll
    for (int o = 16; o > 0; o >>= 1)
        lp += __shfl_xor_sync(0xFFFFFFFFu, lp, o);
    __shared__ float wr[4];
    if ((t & 31) == 0) wr[t >> 5] = lp;
    __syncthreads();
    if (t == 0) {
        double tot = (double)wr[0] + (double)wr[1] + (double)wr[2] + (double)wr[3];
        atomicAdd(&g_s.loss, tot);
        __threadfence();
        int k = atomicAdd(&g_s.ticket, 1);
        if (k == NUM_CLASSES - 1) {
            double total = atomicAdd(&g_s.loss, 0.0);   // coherent read
            out[0] = (float)(0.5 * total / (double)BATCH);
        }
    }
}

extern "C" void kernel_launch(void* const* d_in, const int* in_sizes, int n_in,
                              void* d_out, int out_size) {
    const float* features = (const float*)d_in[0];
    const void*  labels   = d_in[1];
    const float* centers  = (const float*)d_in[2];
    float* out = (float*)d_out;

    void* sp = nullptr;
    cudaGetSymbolAddress(&sp, g_s);
    cudaMemsetAsync(sp, 0, sizeof(Scratch));

    k_front<<<NB, NT>>>(labels);
    k_main<<<NUM_CLASSES, 128>>>((const float4*)features, (const float4*)centers, out);
}

// round 6
// speedup vs baseline: 1.0809x; 1.0708x over previous
#include <cuda_runtime.h>
#include <cuda_bf16.h>
#include <cstdint>

#define NUM_CLASSES 1000
#define FEAT_DIM    512
#define BATCH       32768
#define ALPHA       0.5f

#define GRID   1000          // one block per class; all resident in wave 1 (<= 8/SM * 148)
#define NTHR   128
#define NFRONT 256           // blocks 0..255 handle the 32768 labels (128 rows each)

// -------- scratch (zeroed each replay by the memset node) --------
struct Scratch {
    double   loss;
    int      ticket;
    int      pad0[12];
    unsigned bar_arrive;      // own cacheline
    int      pad1[31];
    unsigned bar_release;     // own cacheline (polled)
    int      pad2[31];
    int      counts[NUM_CLASSES];
    int      cursor[NUM_CLASSES];
};
__device__ Scratch g_s;
__device__ int g_offsets[NUM_CLASSES + 1];
__device__ int g_idx[BATCH];

// -------- software grid barrier: all GRID blocks resident --------
__device__ __forceinline__ void grid_bar(unsigned gen) {
    __syncthreads();
    if (threadIdx.x == 0) {
        __threadfence();
        unsigned t = atomicAdd(&g_s.bar_arrive, 1u) + 1u;
        if (t == (unsigned)GRID * gen) {
            atomicExch(&g_s.bar_release, gen);
        } else {
            volatile unsigned* rel = &g_s.bar_release;
            while (*rel < gen) { __nanosleep(128); }
        }
        __threadfence();
    }
    __syncthreads();
}

// ===================== single cooperative kernel =====================
__global__ void __launch_bounds__(NTHR, 8) k_all(
    const float4* __restrict__ feat,   // [BATCH * 128] float4
    const float4* __restrict__ cen,    // [NUM_CLASSES * 128] float4
    const void*   __restrict__ labels,
    float* __restrict__ out)
{
    const int b = blockIdx.x;
    const int t = threadIdx.x;                 // 0..127

    // prefetch this class's center immediately (independent of all phases)
    float4 c4 = cen[b * 128 + t];

    __shared__ int s_f32;
    int myc = -1;                              // this thread's label (front blocks)

    // ---------------- Phase A: block-local dtype detect + histogram ----------------
    if (b < NFRONT) {
        // Detect: sample 64 odd int32 words from rows < 16384 (in-bounds for both
        // widths: word index <= 2*16383+1 < 32768 = min word count).
        // int64 labels (<1000) -> odd words all 0. int32 -> some nonzero
        // (P[all 64 zero] ~ 1000^-64).
        if (t == 0) s_f32 = 0;
        __syncthreads();
        if (t < 64) {
            int r = (b & (NFRONT / 2 - 1)) * 128 + 2 * t + 1;   // row < 16384
            int w = ((const int*)labels)[2 * r + 1];
            if (__ballot_sync(0xFFFFFFFFu, w != 0)) {
                if ((t & 31) == 0) s_f32 = 1;
            }
        }
        __syncthreads();
        const int f32 = s_f32;

        int row = b * NTHR + t;                // 0..32767
        myc = f32 ? ((const int*)labels)[row]
                  : (int)(((const long long*)labels)[row]);
        atomicAdd(&g_s.counts[myc], 1);
    }
    grid_bar(1);

    // ---------------- Phase B: exclusive scan over 1000 counts (block 0) ----------------
    if (b == 0) {
        __shared__ int ts[NTHR];
        const int base = 8 * t;                // 8 classes per thread
        int v[8], inc[8];
        #pragma unroll
        for (int k = 0; k < 8; k++)
            v[k] = (base + k < NUM_CLASSES) ? g_s.counts[base + k] : 0;
        inc[0] = v[0];
        #pragma unroll
        for (int k = 1; k < 8; k++) inc[k] = inc[k - 1] + v[k];
        ts[t] = inc[7];
        __syncthreads();
        for (int off = 1; off < NTHR; off <<= 1) {
            int x = (t >= off) ? ts[t - off] : 0;
            __syncthreads();
            ts[t] += x;
            __syncthreads();
        }
        int excl = (t > 0) ? ts[t - 1] : 0;
        #pragma unroll
        for (int k = 0; k < 8; k++) {
            if (base + k < NUM_CLASSES) {
                g_offsets[base + k + 1] = excl + inc[k];
                g_s.cursor[base + k]    = excl + inc[k] - v[k];
            }
        }
        if (t == 0) g_offsets[0] = 0;
    }
    grid_bar(2);

    // ---------------- Phase C: scatter (front blocks); others prefetch offsets ----------------
    int beg = 0, end = 0;
    {
        // offsets are final after the scan; load now to hide latency behind scatter
        beg = g_offsets[b];
        end = g_offsets[b + 1];
        if (b < NFRONT) {
            int row = b * NTHR + t;
            int pos = atomicAdd(&g_s.cursor[myc], 1);
            g_idx[pos] = row;
        }
    }
    grid_bar(3);

    // ---------------- Phase D: per-class gather + EMA + loss ----------------
    const int c = b;
    float sx = 0.f, sy = 0.f, sz = 0.f, sw = 0.f;
    float lp = 0.f;

    __shared__ int sidx[256];
    for (int base = beg; base < end; base += 256) {
        int n = min(256, end - base);
        for (int k = t; k < n; k += NTHR) sidx[k] = g_idx[base + k];
        __syncthreads();

        int j = 0;
        for (; j + 8 <= n; j += 8) {
            // front-batched loads: 8 independent LDG.128 in flight
            float4 r[8];
            #pragma unroll
            for (int k = 0; k < 8; k++)
                r[k] = feat[(size_t)sidx[j + k] * 128 + t];
            #pragma unroll
            for (int k = 0; k < 8; k++) {
                sx += r[k].x; sy += r[k].y; sz += r[k].z; sw += r[k].w;
                float dx = r[k].x - c4.x, dy = r[k].y - c4.y;
                float dz = r[k].z - c4.z, dw = r[k].w - c4.w;
                lp += dx * dx + dy * dy + dz * dz + dw * dw;
            }
        }
        for (; j < n; j++) {
            float4 f = feat[(size_t)sidx[j] * 128 + t];
            sx += f.x; sy += f.y; sz += f.z; sw += f.w;
            float dx = f.x - c4.x, dy = f.y - c4.y;
            float dz = f.z - c4.z, dw = f.w - c4.w;
            lp += dx * dx + dy * dy + dz * dz + dw * dw;
        }
        __syncthreads();
    }

    const int cnt = end - beg;
    float4 nc;
    if (cnt > 0) {
        float inv = ALPHA / (float)cnt;
        nc.x = (1.f - ALPHA) * c4.x + sx * inv;
        nc.y = (1.f - ALPHA) * c4.y + sy * inv;
        nc.z = (1.f - ALPHA) * c4.z + sz * inv;
        nc.w = (1.f - ALPHA) * c4.w + sw * inv;
    } else {
        nc = c4;
    }
    // out[0] = loss; out[1..] = new_centers (+1 shift -> scalar stores)
    float* ncp = out + 1 + (size_t)c * FEAT_DIM + t * 4;
    ncp[0] = nc.x; ncp[1] = nc.y; ncp[2] = nc.z; ncp[3] = nc.w;

    // block loss reduce + global accumulate + last-block finalize
    #pragma unroll
    for (int o = 16; o > 0; o >>= 1)
        lp += __shfl_xor_sync(0xFFFFFFFFu, lp, o);
    __shared__ float wr[4];
    if ((t & 31) == 0) wr[t >> 5] = lp;
    __syncthreads();
    if (t == 0) {
        double tot = (double)wr[0] + (double)wr[1] + (double)wr[2] + (double)wr[3];
        atomicAdd(&g_s.loss, tot);
        __threadfence();
        int k = atomicAdd(&g_s.ticket, 1);
        if (k == GRID - 1) {
            double total = atomicAdd(&g_s.loss, 0.0);   // coherent read
            out[0] = (float)(0.5 * total / (double)BATCH);
        }
    }
}

extern "C" void kernel_launch(void* const* d_in, const int* in_sizes, int n_in,
                              void* d_out, int out_size) {
    const float* features = (const float*)d_in[0];
    const void*  labels   = d_in[1];
    const float* centers  = (const float*)d_in[2];
    float* out = (float*)d_out;

    void* sp = nullptr;
    cudaGetSymbolAddress(&sp, g_s);
    cudaMemsetAsync(sp, 0, sizeof(Scratch));

    k_all<<<GRID, NTHR>>>((const float4*)features, (const float4*)centers,
                          labels, out);
}